// round 11
// baseline (speedup 1.0000x reference)
#include <cuda_runtime.h>

#define NN 100000
#define NE 1600000
#define DIM 128
#define DC 64
#define BN_EPS 1e-5f
#define SCAN_B 1024
#define NB ((NN + SCAN_B - 1) / SCAN_B)   // 98

// ---------------- f32x2 packed-math helpers ---------------------------------
typedef unsigned long long u64;

__device__ __forceinline__ u64 pack2(float lo, float hi) {
    u64 r;
    asm("mov.b64 %0, {%1, %2};" : "=l"(r) : "f"(lo), "f"(hi));
    return r;
}
__device__ __forceinline__ void unpack2(u64 v, float& lo, float& hi) {
    asm("mov.b64 {%0, %1}, %2;" : "=f"(lo), "=f"(hi) : "l"(v));
}
#define FMA2(acc, a, b) \
    asm("fma.rn.f32x2 %0, %1, %2, %0;" : "+l"(acc) : "l"(a), "l"(b))

// ---------------- scratch (device globals; zero-initialized at load) -------
__device__ float g_buf_agg[NN * DIM];
__device__ float g_buf_h[NN * DIM];
__device__ float g_norm_src[NN];
__device__ float g_norm_dst[NN];
__device__ float g_sns[NN];             // written by pull_l1 (plain store)
__device__ int   g_deg_out[NN];         // reset tail
__device__ int   g_deg_in[NN];          // reset tail
__device__ int   g_off[NN];
__device__ int   g_blockoff[NB];
__device__ int   g_blocksum[NB];
__device__ int   g_cursor[NN];          // reset tail
__device__ int   g_csr_src[NE];
__device__ u64   g_Wp0[64 * DIM];       // k-pair packed weights
__device__ u64   g_Wp1[64 * DIM];
__device__ u64   g_Wp2[64 * DC];
__device__ float g_sum0[DIM], g_sumsq0[DIM];
__device__ float g_sum1[DIM], g_sumsq1[DIM];

#define BUF_AGG 0
#define BUF_H   1
__device__ __forceinline__ const float* buf_sel(int s) {
    return (s == BUF_AGG) ? g_buf_agg : g_buf_h;
}
__device__ __forceinline__ float* buf_sel_w(int s) {
    return (s == BUF_AGG) ? g_buf_agg : g_buf_h;
}
__device__ __forceinline__ int csr_start(int node) {
    return g_off[node] + g_blockoff[node >> 10];
}

// ---------------- setup -------------------------------------------------------
__global__ void k_count(const int* __restrict__ src, const int* __restrict__ dst) {
    int e = blockIdx.x * blockDim.x + threadIdx.x;
    if (e < NE) {
        atomicAdd(&g_deg_out[src[e]], 1);
        atomicAdd(&g_deg_in[dst[e]], 1);
    }
}

__global__ void __launch_bounds__(SCAN_B) k_scan_norms() {
    __shared__ int s[SCAN_B];
    int i = blockIdx.x * SCAN_B + threadIdx.x;
    int din = (i < NN) ? g_deg_in[i] : 0;
    s[threadIdx.x] = din;
    __syncthreads();
    #pragma unroll
    for (int off = 1; off < SCAN_B; off <<= 1) {
        int v = (threadIdx.x >= off) ? s[threadIdx.x - off] : 0;
        __syncthreads();
        s[threadIdx.x] += v;
        __syncthreads();
    }
    if (i < NN) {
        g_off[i] = s[threadIdx.x] - din;
        g_norm_src[i] = rsqrtf(fmaxf((float)g_deg_out[i], 1.0f));
        g_norm_dst[i] = rsqrtf(fmaxf((float)din, 1.0f));
    }
    if (threadIdx.x == SCAN_B - 1) g_blocksum[blockIdx.x] = s[SCAN_B - 1];
    if (blockIdx.x == 0 && threadIdx.x < DIM) {
        g_sum0[threadIdx.x] = 0.f; g_sumsq0[threadIdx.x] = 0.f;
        g_sum1[threadIdx.x] = 0.f; g_sumsq1[threadIdx.x] = 0.f;
    }
}

__global__ void k_scan_block() {
    __shared__ int s[NB];
    if (threadIdx.x < NB) s[threadIdx.x] = g_blocksum[threadIdx.x];
    __syncthreads();
    if (threadIdx.x == 0) {
        int acc = 0;
        for (int b = 0; b < NB; ++b) { int v = s[b]; s[b] = acc; acc += v; }
    }
    __syncthreads();
    if (threadIdx.x < NB) g_blockoff[threadIdx.x] = s[threadIdx.x];
}

// CSR fill (single atomic per edge; sns moved to pull_l1)
__global__ void k_fill_csr(const int* __restrict__ src, const int* __restrict__ dst) {
    int e = blockIdx.x * blockDim.x + threadIdx.x;
    if (e < NE) {
        int d = dst[e];
        int pos = atomicAdd(&g_cursor[d], 1);
        g_csr_src[g_off[d] + g_blockoff[d >> 10] + pos] = src[e];
    }
}

// pack all three weight matrices into k-pair u64 layout
__global__ void k_packW(const float* __restrict__ W0, const float* __restrict__ W1,
                        const float* __restrict__ W2) {
    int i = blockIdx.x * blockDim.x + threadIdx.x;
    if (i < 64 * DIM) {
        int k2 = i / DIM, c = i % DIM;
        g_Wp0[i] = pack2(W0[(2 * k2) * DIM + c], W0[(2 * k2 + 1) * DIM + c]);
        g_Wp1[i] = pack2(W1[(2 * k2) * DIM + c], W1[(2 * k2 + 1) * DIM + c]);
    }
    if (i < 64 * DC) {
        int k2 = i / DC, c = i % DC;
        g_Wp2[i] = pack2(W2[(2 * k2) * DC + c], W2[(2 * k2 + 1) * DC + c]);
    }
}

// ---------------- pull, layer 1 (raw features; also emits sns) ----------------
__global__ void __launch_bounds__(256) k_pull128_l1(const float* __restrict__ h) {
    int t = blockIdx.x * blockDim.x + threadIdx.x;
    int node = t >> 5;
    if (node >= NN) return;
    int lane = t & 31;
    int c = lane << 2;
    int start = csr_start(node);
    int n = g_deg_in[node];

    float4 a0 = make_float4(0.f, 0.f, 0.f, 0.f);
    float4 a1 = make_float4(0.f, 0.f, 0.f, 0.f);
    float sns = 0.f;

    int j = 0;
    int end4 = n & ~3;
    for (; j < end4; j += 4) {
        int s0 = __ldg(&g_csr_src[start + j]);
        int s1 = __ldg(&g_csr_src[start + j + 1]);
        int s2 = __ldg(&g_csr_src[start + j + 2]);
        int s3 = __ldg(&g_csr_src[start + j + 3]);
        float n0 = __ldg(&g_norm_src[s0]);
        float n1 = __ldg(&g_norm_src[s1]);
        float n2 = __ldg(&g_norm_src[s2]);
        float n3 = __ldg(&g_norm_src[s3]);
        float4 v0 = *reinterpret_cast<const float4*>(h + (size_t)s0 * DIM + c);
        float4 v1 = *reinterpret_cast<const float4*>(h + (size_t)s1 * DIM + c);
        float4 v2 = *reinterpret_cast<const float4*>(h + (size_t)s2 * DIM + c);
        float4 v3 = *reinterpret_cast<const float4*>(h + (size_t)s3 * DIM + c);
        a0.x = fmaf(n0, v0.x, a0.x); a0.y = fmaf(n0, v0.y, a0.y);
        a0.z = fmaf(n0, v0.z, a0.z); a0.w = fmaf(n0, v0.w, a0.w);
        a1.x = fmaf(n1, v1.x, a1.x); a1.y = fmaf(n1, v1.y, a1.y);
        a1.z = fmaf(n1, v1.z, a1.z); a1.w = fmaf(n1, v1.w, a1.w);
        a0.x = fmaf(n2, v2.x, a0.x); a0.y = fmaf(n2, v2.y, a0.y);
        a0.z = fmaf(n2, v2.z, a0.z); a0.w = fmaf(n2, v2.w, a0.w);
        a1.x = fmaf(n3, v3.x, a1.x); a1.y = fmaf(n3, v3.y, a1.y);
        a1.z = fmaf(n3, v3.z, a1.z); a1.w = fmaf(n3, v3.w, a1.w);
        sns += (n0 + n1) + (n2 + n3);
    }
    for (; j < n; ++j) {
        int s0 = __ldg(&g_csr_src[start + j]);
        float n0 = __ldg(&g_norm_src[s0]);
        float4 v0 = *reinterpret_cast<const float4*>(h + (size_t)s0 * DIM + c);
        a0.x = fmaf(n0, v0.x, a0.x); a0.y = fmaf(n0, v0.y, a0.y);
        a0.z = fmaf(n0, v0.z, a0.z); a0.w = fmaf(n0, v0.w, a0.w);
        sns += n0;
    }
    a0.x += a1.x; a0.y += a1.y; a0.z += a1.z; a0.w += a1.w;

    float nd = g_norm_dst[node];
    a0.x *= nd; a0.y *= nd; a0.z *= nd; a0.w *= nd;
    *reinterpret_cast<float4*>(g_buf_agg + (size_t)node * DIM + c) = a0;
    if (lane == 0) g_sns[node] = sns;     // all lanes hold identical sum
}

// ---------------- pull, layer 2 (pure row-sum; BN stats finalized inline) ----
__global__ void __launch_bounds__(256) k_pull128_fast() {
    int t = blockIdx.x * blockDim.x + threadIdx.x;
    int node = t >> 5;
    if (node >= NN) return;
    const float* __restrict__ h = g_buf_h;
    int lane = t & 31;
    int c = lane << 2;

    // finalize BN stats for this lane's 4 columns (from layer-1 sums)
    const float inv = 1.0f / (float)NN;
    float4 S = *reinterpret_cast<const float4*>(g_sum0 + c);
    float4 Q = *reinterpret_cast<const float4*>(g_sumsq0 + c);
    float4 m, rs;
    m.x = S.x * inv; m.y = S.y * inv; m.z = S.z * inv; m.w = S.w * inv;
    rs.x = rsqrtf(fmaxf(Q.x * inv - m.x * m.x, 0.f) + BN_EPS);
    rs.y = rsqrtf(fmaxf(Q.y * inv - m.y * m.y, 0.f) + BN_EPS);
    rs.z = rsqrtf(fmaxf(Q.z * inv - m.z * m.z, 0.f) + BN_EPS);
    rs.w = rsqrtf(fmaxf(Q.w * inv - m.w * m.w, 0.f) + BN_EPS);

    int start = csr_start(node);
    int n = g_deg_in[node];

    float4 a0 = make_float4(0.f, 0.f, 0.f, 0.f);
    float4 a1 = make_float4(0.f, 0.f, 0.f, 0.f);

    int j = 0;
    int end4 = n & ~3;
    for (; j < end4; j += 4) {
        int s0 = __ldg(&g_csr_src[start + j]);
        int s1 = __ldg(&g_csr_src[start + j + 1]);
        int s2 = __ldg(&g_csr_src[start + j + 2]);
        int s3 = __ldg(&g_csr_src[start + j + 3]);
        float4 v0 = *reinterpret_cast<const float4*>(h + (size_t)s0 * DIM + c);
        float4 v1 = *reinterpret_cast<const float4*>(h + (size_t)s1 * DIM + c);
        float4 v2 = *reinterpret_cast<const float4*>(h + (size_t)s2 * DIM + c);
        float4 v3 = *reinterpret_cast<const float4*>(h + (size_t)s3 * DIM + c);
        a0.x += v0.x + v2.x; a0.y += v0.y + v2.y;
        a0.z += v0.z + v2.z; a0.w += v0.w + v2.w;
        a1.x += v1.x + v3.x; a1.y += v1.y + v3.y;
        a1.z += v1.z + v3.z; a1.w += v1.w + v3.w;
    }
    for (; j < n; ++j) {
        int s0 = __ldg(&g_csr_src[start + j]);
        float4 v0 = *reinterpret_cast<const float4*>(h + (size_t)s0 * DIM + c);
        a0.x += v0.x; a0.y += v0.y; a0.z += v0.z; a0.w += v0.w;
    }
    a0.x += a1.x; a0.y += a1.y; a0.z += a1.z; a0.w += a1.w;

    float sns = g_sns[node];
    float nd  = g_norm_dst[node];
    a0.x = (a0.x - m.x * sns) * rs.x * nd;
    a0.y = (a0.y - m.y * sns) * rs.y * nd;
    a0.z = (a0.z - m.z * sns) * rs.z * nd;
    a0.w = (a0.w - m.w * sns) * rs.w * nd;
    *reinterpret_cast<float4*>(g_buf_agg + (size_t)node * DIM + c) = a0;
}

// ---------------- pull, final layer (64 wide) ---------------------------------
__global__ void __launch_bounds__(256) k_pull64(float* __restrict__ out,
                                                const float* __restrict__ b2) {
    int t = blockIdx.x * blockDim.x + threadIdx.x;
    int node = t >> 4;
    if (node >= NN) return;
    const float* __restrict__ g = g_buf_agg;
    int lane = t & 15;
    int c = lane << 2;
    int start = csr_start(node);
    int n = g_deg_in[node];

    float4 a0 = make_float4(0.f, 0.f, 0.f, 0.f);
    float4 a1 = make_float4(0.f, 0.f, 0.f, 0.f);

    int j = 0;
    int end4 = n & ~3;
    for (; j < end4; j += 4) {
        int s0 = __ldg(&g_csr_src[start + j]);
        int s1 = __ldg(&g_csr_src[start + j + 1]);
        int s2 = __ldg(&g_csr_src[start + j + 2]);
        int s3 = __ldg(&g_csr_src[start + j + 3]);
        float4 v0 = *reinterpret_cast<const float4*>(g + (size_t)s0 * DC + c);
        float4 v1 = *reinterpret_cast<const float4*>(g + (size_t)s1 * DC + c);
        float4 v2 = *reinterpret_cast<const float4*>(g + (size_t)s2 * DC + c);
        float4 v3 = *reinterpret_cast<const float4*>(g + (size_t)s3 * DC + c);
        a0.x += v0.x + v2.x; a0.y += v0.y + v2.y;
        a0.z += v0.z + v2.z; a0.w += v0.w + v2.w;
        a1.x += v1.x + v3.x; a1.y += v1.y + v3.y;
        a1.z += v1.z + v3.z; a1.w += v1.w + v3.w;
    }
    for (; j < n; ++j) {
        int s0 = __ldg(&g_csr_src[start + j]);
        float4 v0 = *reinterpret_cast<const float4*>(g + (size_t)s0 * DC + c);
        a0.x += v0.x; a0.y += v0.y; a0.z += v0.z; a0.w += v0.w;
    }
    a0.x += a1.x; a0.y += a1.y; a0.z += a1.z; a0.w += a1.w;

    float nd = g_norm_dst[node];
    float4 b = *reinterpret_cast<const float4*>(b2 + c);
    a0.x = fmaf(a0.x, nd, b.x);
    a0.y = fmaf(a0.y, nd, b.y);
    a0.z = fmaf(a0.z, nd, b.z);
    a0.w = fmaf(a0.w, nd, b.w);
    *reinterpret_cast<float4*>(out + (size_t)node * DC + c) = a0;
}

// ---------------- fused GEMM (k-pair packed f32x2, zero pack overhead) --------
// WSEL selects packed weights. XFORM=1: (v - mean*ns[row])*rstd with mean/rstd
// finalized inline from g_sum1/g_sumsq1. OUT_SCALE: store *= ns[row].
// STATS: -1 none, 0 -> sum0, 1 -> sum1.
template<int OUTW, int IN_SEL, int OUT_SEL, int WSEL, int XFORM, bool BIAS_RELU, bool OUT_SCALE, int STATS>
__global__ void __launch_bounds__(256) k_gemm(const float* __restrict__ bias) {
    constexpr int CT = OUTW / 16;       // cols per thread (8 or 4)
    __shared__ float As[64 * 132];

    const float* __restrict__ A = buf_sel(IN_SEL);
    float* __restrict__ out = buf_sel_w(OUT_SEL);
    const u64* __restrict__ Wp = (WSEL == 0) ? g_Wp0 : (WSEL == 1) ? g_Wp1 : g_Wp2;

    int rowBase = blockIdx.x * 64;

    #pragma unroll
    for (int it = 0; it < 8; ++it) {
        int idx = threadIdx.x + it * 256;
        int r   = idx >> 5;
        int c   = (idx & 31) << 2;
        int row = rowBase + r;
        float4 v = make_float4(0.f, 0.f, 0.f, 0.f);
        if (row < NN) {
            v = *reinterpret_cast<const float4*>(A + (size_t)row * DIM + c);
            if (XFORM == 1) {
                const float inv = 1.0f / (float)NN;
                float ns = g_norm_src[row];
                float4 S = *reinterpret_cast<const float4*>(g_sum1 + c);
                float4 Q = *reinterpret_cast<const float4*>(g_sumsq1 + c);
                float mx = S.x * inv, my = S.y * inv, mz = S.z * inv, mw = S.w * inv;
                float rx = rsqrtf(fmaxf(Q.x * inv - mx * mx, 0.f) + BN_EPS);
                float ry = rsqrtf(fmaxf(Q.y * inv - my * my, 0.f) + BN_EPS);
                float rz = rsqrtf(fmaxf(Q.z * inv - mz * mz, 0.f) + BN_EPS);
                float rw = rsqrtf(fmaxf(Q.w * inv - mw * mw, 0.f) + BN_EPS);
                v.x = (v.x - mx * ns) * rx;
                v.y = (v.y - my * ns) * ry;
                v.z = (v.z - mz * ns) * rz;
                v.w = (v.w - mw * ns) * rw;
            }
        }
        *reinterpret_cast<float4*>(&As[r * 132 + c]) = v;
    }
    __syncthreads();

    int tr = threadIdx.x >> 4;
    int tc = threadIdx.x & 15;
    const float* A0 = &As[(tr * 4) * 132];

    u64 acc[4][CT];                     // (even-k partial, odd-k partial)
    #pragma unroll
    for (int i = 0; i < 4; ++i)
        #pragma unroll
        for (int j = 0; j < CT; ++j) acc[i][j] = 0ull;

    const u64* wbase = Wp + tc * CT;

    #pragma unroll 2
    for (int k2 = 0; k2 < 64; ++k2) {
        // A pair (A[2k2], A[2k2+1]) loaded directly as u64 — no MOV packing
        u64 a0 = *reinterpret_cast<const u64*>(A0 + 2 * k2);
        u64 a1 = *reinterpret_cast<const u64*>(A0 + 132 + 2 * k2);
        u64 a2 = *reinterpret_cast<const u64*>(A0 + 264 + 2 * k2);
        u64 a3 = *reinterpret_cast<const u64*>(A0 + 396 + 2 * k2);
        const u64* wrow = wbase + k2 * OUTW;
        u64 w[CT];
        asm("ld.global.nc.v2.u64 {%0, %1}, [%2];"
            : "=l"(w[0]), "=l"(w[1]) : "l"(wrow));
        asm("ld.global.nc.v2.u64 {%0, %1}, [%2];"
            : "=l"(w[2]), "=l"(w[3]) : "l"(wrow + 2));
        if (CT == 8) {
            asm("ld.global.nc.v2.u64 {%0, %1}, [%2];"
                : "=l"(w[4]), "=l"(w[5]) : "l"(wrow + 4));
            asm("ld.global.nc.v2.u64 {%0, %1}, [%2];"
                : "=l"(w[6]), "=l"(w[7]) : "l"(wrow + 6));
        }
        #pragma unroll
        for (int j = 0; j < CT; ++j) {
            FMA2(acc[0][j], a0, w[j]);
            FMA2(acc[1][j], a1, w[j]);
            FMA2(acc[2][j], a2, w[j]);
            FMA2(acc[3][j], a3, w[j]);
        }
    }

    // epilogue: merge even/odd partials, bias+relu, store; keep for stats
    float res[4][CT];
    float bv[CT];
    if (BIAS_RELU) {
        #pragma unroll
        for (int j0 = 0; j0 < CT; j0 += 4) {
            float4 b = __ldg(reinterpret_cast<const float4*>(bias + tc * CT + j0));
            bv[j0] = b.x; bv[j0 + 1] = b.y; bv[j0 + 2] = b.z; bv[j0 + 3] = b.w;
        }
    }
    #pragma unroll
    for (int i = 0; i < 4; ++i) {
        int row = rowBase + tr * 4 + i;
        bool valid = row < NN;
        #pragma unroll
        for (int j = 0; j < CT; ++j) {
            float lo, hi;
            unpack2(acc[i][j], lo, hi);
            float y = lo + hi;
            if (BIAS_RELU) y = fmaxf(y + bv[j], 0.f);
            res[i][j] = valid ? y : 0.f;
        }
        if (valid) {
            float osc = OUT_SCALE ? __ldg(&g_norm_src[row]) : 1.0f;
            #pragma unroll
            for (int j0 = 0; j0 < CT; j0 += 4) {
                float4 y4;
                y4.x = res[i][j0 + 0] * osc; y4.y = res[i][j0 + 1] * osc;
                y4.z = res[i][j0 + 2] * osc; y4.w = res[i][j0 + 3] * osc;
                *reinterpret_cast<float4*>(out + (size_t)row * OUTW + tc * CT + j0) = y4;
            }
        }
    }

    if (STATS >= 0) {
        float* SUM = (STATS == 0) ? g_sum0 : g_sum1;
        float* SQ  = (STATS == 0) ? g_sumsq0 : g_sumsq1;
        float* sh = As;
        __syncthreads();
        #pragma unroll
        for (int j = 0; j < CT; ++j) {
            float s = (res[0][j] + res[1][j]) + (res[2][j] + res[3][j]);
            float q = fmaf(res[0][j], res[0][j],
                      fmaf(res[1][j], res[1][j],
                      fmaf(res[2][j], res[2][j], res[3][j] * res[3][j])));
            int col = tc * CT + j;
            sh[tr * 128 + col] = s;
            sh[2048 + tr * 128 + col] = q;
        }
        __syncthreads();
        if (threadIdx.x < 128) {
            int col = threadIdx.x;
            float s = 0.f, q = 0.f;
            #pragma unroll
            for (int k2 = 0; k2 < 16; ++k2) {
                s += sh[k2 * 128 + col];
                q += sh[2048 + k2 * 128 + col];
            }
            atomicAdd(&SUM[col], s);
            atomicAdd(&SQ[col], q);
        }
    }
}

// ---------------- tail reset ----------------------------------------------------
__global__ void k_reset() {
    int i = blockIdx.x * blockDim.x + threadIdx.x;
    if (i < NN) {
        g_deg_out[i] = 0; g_deg_in[i] = 0; g_cursor[i] = 0;
    }
}

// ---------------- launch ---------------------------------------------------------
extern "C" void kernel_launch(void* const* d_in, const int* in_sizes, int n_in,
                              void* d_out, int out_size) {
    const float* features = (const float*)d_in[0];
    const float* W0 = (const float*)d_in[1];
    const float* b0 = (const float*)d_in[2];
    const float* W1 = (const float*)d_in[3];
    const float* b1 = (const float*)d_in[4];
    const float* W2 = (const float*)d_in[5];
    const float* b2 = (const float*)d_in[6];
    const int* src = (const int*)d_in[7];
    const int* dst = (const int*)d_in[8];
    float* out = (float*)d_out;

    const int TB = 256;
    const int gN      = (NN + TB - 1) / TB;
    const int gE      = (NE + TB - 1) / TB;
    const int gPull   = (NN * 32 + TB - 1) / TB;
    const int gPull64 = (NN * 16 + TB - 1) / TB;
    const int gGemm   = (NN + 63) / 64;
    const int gPack   = (64 * DIM + TB - 1) / TB;

    // setup (counters arrive zeroed: zero-init first call, k_reset tail after)
    k_count<<<gE, TB>>>(src, dst);          // #1
    k_scan_norms<<<NB, SCAN_B>>>();         // #2
    k_scan_block<<<1, 128>>>();             // #3
    k_fill_csr<<<gE, TB>>>(src, dst);       // #4 (profiled slot)
    k_packW<<<gPack, TB>>>(W0, W1, W2);     // #5

    // layer 1: agg = nd * A~(ns*feat) (+ sns); h' = ns*relu(agg@W0+b0); stats->0
    k_pull128_l1<<<gPull, TB>>>(features);
    k_gemm<128, BUF_AGG, BUF_H, 0, 0, true, true, 0><<<gGemm, TB>>>(b0);

    // layer 2: pure-sum pull (BN finalized inline); h' = ns*relu(...); stats->1
    k_pull128_fast<<<gPull, TB>>>();
    k_gemm<128, BUF_AGG, BUF_H, 1, 0, true, true, 1><<<gGemm, TB>>>(b1);

    // layer 3: g = ((h' - m*ns)*rs) @ W2 (BN finalized inline), then pull64
    k_gemm<64, BUF_H, BUF_AGG, 2, 1, false, false, -1><<<gGemm, TB>>>(nullptr);
    k_pull64<<<gPull64, TB>>>(out, b2);

    // leave counters zeroed for next invocation
    k_reset<<<gN, TB>>>();
}

// round 12
// speedup vs baseline: 1.3004x; 1.3004x over previous
#include <cuda_runtime.h>

#define NN 100000
#define NE 1600000
#define DIM 128
#define DC 64
#define BN_EPS 1e-5f
#define SCAN_B 1024
#define NB ((NN + SCAN_B - 1) / SCAN_B)   // 98

// ---------------- f32x2 packed-math helpers ---------------------------------
typedef unsigned long long u64;

__device__ __forceinline__ u64 pack_dup(float v) {
    u64 r;
    asm("mov.b64 %0, {%1, %1};" : "=l"(r) : "f"(v));
    return r;
}
__device__ __forceinline__ void unpack2(u64 v, float& lo, float& hi) {
    asm("mov.b64 {%0, %1}, %2;" : "=f"(lo), "=f"(hi) : "l"(v));
}
#define FMA2(acc, a, b) \
    asm("fma.rn.f32x2 %0, %1, %2, %0;" : "+l"(acc) : "l"(a), "l"(b))

// ---------------- scratch (device globals; zero-initialized at load) -------
__device__ float g_buf_agg[NN * DIM];
__device__ float g_buf_h[NN * DIM];
__device__ float g_norm_src[NN];
__device__ float g_norm_dst[NN];
__device__ float g_sns[NN];             // written by pull_l1 (plain store)
__device__ int   g_deg_out[NN];         // reset tail
__device__ int   g_deg_in[NN];          // reset tail
__device__ int   g_off[NN];
__device__ int   g_blockoff[NB];
__device__ int   g_blocksum[NB];
__device__ int   g_cursor[NN];          // reset tail
__device__ int   g_csr_src[NE];
__device__ float g_sum0[DIM], g_sumsq0[DIM];
__device__ float g_sum1[DIM], g_sumsq1[DIM];
__device__ float g_mean[DIM], g_rstd[DIM];

#define BUF_AGG 0
#define BUF_H   1
__device__ __forceinline__ const float* buf_sel(int s) {
    return (s == BUF_AGG) ? g_buf_agg : g_buf_h;
}
__device__ __forceinline__ float* buf_sel_w(int s) {
    return (s == BUF_AGG) ? g_buf_agg : g_buf_h;
}
__device__ __forceinline__ int csr_start(int node) {
    return g_off[node] + g_blockoff[node >> 10];
}

// ---------------- setup -------------------------------------------------------
__global__ void k_count(const int* __restrict__ src, const int* __restrict__ dst) {
    int e = blockIdx.x * blockDim.x + threadIdx.x;
    if (e < NE) {
        atomicAdd(&g_deg_out[src[e]], 1);
        atomicAdd(&g_deg_in[dst[e]], 1);
    }
}

__global__ void __launch_bounds__(SCAN_B) k_scan_norms() {
    __shared__ int s[SCAN_B];
    int i = blockIdx.x * SCAN_B + threadIdx.x;
    int din = (i < NN) ? g_deg_in[i] : 0;
    s[threadIdx.x] = din;
    __syncthreads();
    #pragma unroll
    for (int off = 1; off < SCAN_B; off <<= 1) {
        int v = (threadIdx.x >= off) ? s[threadIdx.x - off] : 0;
        __syncthreads();
        s[threadIdx.x] += v;
        __syncthreads();
    }
    if (i < NN) {
        g_off[i] = s[threadIdx.x] - din;
        g_norm_src[i] = rsqrtf(fmaxf((float)g_deg_out[i], 1.0f));
        g_norm_dst[i] = rsqrtf(fmaxf((float)din, 1.0f));
    }
    if (threadIdx.x == SCAN_B - 1) g_blocksum[blockIdx.x] = s[SCAN_B - 1];
    if (blockIdx.x == 0 && threadIdx.x < DIM) {
        g_sum0[threadIdx.x] = 0.f; g_sumsq0[threadIdx.x] = 0.f;
        g_sum1[threadIdx.x] = 0.f; g_sumsq1[threadIdx.x] = 0.f;
    }
}

__global__ void k_scan_block() {
    __shared__ int s[NB];
    if (threadIdx.x < NB) s[threadIdx.x] = g_blocksum[threadIdx.x];
    __syncthreads();
    if (threadIdx.x == 0) {
        int acc = 0;
        for (int b = 0; b < NB; ++b) { int v = s[b]; s[b] = acc; acc += v; }
    }
    __syncthreads();
    if (threadIdx.x < NB) g_blockoff[threadIdx.x] = s[threadIdx.x];
}

// CSR fill (single atomic per edge; sns computed in pull_l1)
__global__ void k_fill_csr(const int* __restrict__ src, const int* __restrict__ dst) {
    int e = blockIdx.x * blockDim.x + threadIdx.x;
    if (e < NE) {
        int d = dst[e];
        int pos = atomicAdd(&g_cursor[d], 1);
        g_csr_src[g_off[d] + g_blockoff[d >> 10] + pos] = src[e];
    }
}

// ---------------- pull, layer 1 (raw features; also emits sns) ----------------
__global__ void __launch_bounds__(256) k_pull128_l1(const float* __restrict__ h) {
    int t = blockIdx.x * blockDim.x + threadIdx.x;
    int node = t >> 5;
    if (node >= NN) return;
    int lane = t & 31;
    int c = lane << 2;
    int start = csr_start(node);
    int n = g_deg_in[node];

    float4 a0 = make_float4(0.f, 0.f, 0.f, 0.f);
    float4 a1 = make_float4(0.f, 0.f, 0.f, 0.f);
    float sns = 0.f;

    int j = 0;
    int end4 = n & ~3;
    for (; j < end4; j += 4) {
        int s0 = __ldg(&g_csr_src[start + j]);
        int s1 = __ldg(&g_csr_src[start + j + 1]);
        int s2 = __ldg(&g_csr_src[start + j + 2]);
        int s3 = __ldg(&g_csr_src[start + j + 3]);
        float n0 = __ldg(&g_norm_src[s0]);
        float n1 = __ldg(&g_norm_src[s1]);
        float n2 = __ldg(&g_norm_src[s2]);
        float n3 = __ldg(&g_norm_src[s3]);
        float4 v0 = *reinterpret_cast<const float4*>(h + (size_t)s0 * DIM + c);
        float4 v1 = *reinterpret_cast<const float4*>(h + (size_t)s1 * DIM + c);
        float4 v2 = *reinterpret_cast<const float4*>(h + (size_t)s2 * DIM + c);
        float4 v3 = *reinterpret_cast<const float4*>(h + (size_t)s3 * DIM + c);
        a0.x = fmaf(n0, v0.x, a0.x); a0.y = fmaf(n0, v0.y, a0.y);
        a0.z = fmaf(n0, v0.z, a0.z); a0.w = fmaf(n0, v0.w, a0.w);
        a1.x = fmaf(n1, v1.x, a1.x); a1.y = fmaf(n1, v1.y, a1.y);
        a1.z = fmaf(n1, v1.z, a1.z); a1.w = fmaf(n1, v1.w, a1.w);
        a0.x = fmaf(n2, v2.x, a0.x); a0.y = fmaf(n2, v2.y, a0.y);
        a0.z = fmaf(n2, v2.z, a0.z); a0.w = fmaf(n2, v2.w, a0.w);
        a1.x = fmaf(n3, v3.x, a1.x); a1.y = fmaf(n3, v3.y, a1.y);
        a1.z = fmaf(n3, v3.z, a1.z); a1.w = fmaf(n3, v3.w, a1.w);
        sns += (n0 + n1) + (n2 + n3);
    }
    for (; j < n; ++j) {
        int s0 = __ldg(&g_csr_src[start + j]);
        float n0 = __ldg(&g_norm_src[s0]);
        float4 v0 = *reinterpret_cast<const float4*>(h + (size_t)s0 * DIM + c);
        a0.x = fmaf(n0, v0.x, a0.x); a0.y = fmaf(n0, v0.y, a0.y);
        a0.z = fmaf(n0, v0.z, a0.z); a0.w = fmaf(n0, v0.w, a0.w);
        sns += n0;
    }
    a0.x += a1.x; a0.y += a1.y; a0.z += a1.z; a0.w += a1.w;

    float nd = g_norm_dst[node];
    a0.x *= nd; a0.y *= nd; a0.z *= nd; a0.w *= nd;
    *reinterpret_cast<float4*>(g_buf_agg + (size_t)node * DIM + c) = a0;
    if (lane == 0) g_sns[node] = sns;     // all lanes hold identical sum
}

// ---------------- pull, layer 2 (pure row-sum; reads precomputed mean/rstd) --
__global__ void __launch_bounds__(256) k_pull128_fast() {
    int t = blockIdx.x * blockDim.x + threadIdx.x;
    int node = t >> 5;
    if (node >= NN) return;
    const float* __restrict__ h = g_buf_h;
    int lane = t & 31;
    int c = lane << 2;
    int start = csr_start(node);
    int n = g_deg_in[node];

    float4 a0 = make_float4(0.f, 0.f, 0.f, 0.f);
    float4 a1 = make_float4(0.f, 0.f, 0.f, 0.f);

    int j = 0;
    int end4 = n & ~3;
    for (; j < end4; j += 4) {
        int s0 = __ldg(&g_csr_src[start + j]);
        int s1 = __ldg(&g_csr_src[start + j + 1]);
        int s2 = __ldg(&g_csr_src[start + j + 2]);
        int s3 = __ldg(&g_csr_src[start + j + 3]);
        float4 v0 = *reinterpret_cast<const float4*>(h + (size_t)s0 * DIM + c);
        float4 v1 = *reinterpret_cast<const float4*>(h + (size_t)s1 * DIM + c);
        float4 v2 = *reinterpret_cast<const float4*>(h + (size_t)s2 * DIM + c);
        float4 v3 = *reinterpret_cast<const float4*>(h + (size_t)s3 * DIM + c);
        a0.x += v0.x + v2.x; a0.y += v0.y + v2.y;
        a0.z += v0.z + v2.z; a0.w += v0.w + v2.w;
        a1.x += v1.x + v3.x; a1.y += v1.y + v3.y;
        a1.z += v1.z + v3.z; a1.w += v1.w + v3.w;
    }
    for (; j < n; ++j) {
        int s0 = __ldg(&g_csr_src[start + j]);
        float4 v0 = *reinterpret_cast<const float4*>(h + (size_t)s0 * DIM + c);
        a0.x += v0.x; a0.y += v0.y; a0.z += v0.z; a0.w += v0.w;
    }
    a0.x += a1.x; a0.y += a1.y; a0.z += a1.z; a0.w += a1.w;

    float sns = g_sns[node];
    float nd  = g_norm_dst[node];
    float4 m  = *reinterpret_cast<const float4*>(g_mean + c);
    float4 rs = *reinterpret_cast<const float4*>(g_rstd + c);
    a0.x = (a0.x - m.x * sns) * rs.x * nd;
    a0.y = (a0.y - m.y * sns) * rs.y * nd;
    a0.z = (a0.z - m.z * sns) * rs.z * nd;
    a0.w = (a0.w - m.w * sns) * rs.w * nd;
    *reinterpret_cast<float4*>(g_buf_agg + (size_t)node * DIM + c) = a0;
}

// ---------------- pull, final layer (64 wide) ---------------------------------
__global__ void __launch_bounds__(256) k_pull64(float* __restrict__ out,
                                                const float* __restrict__ b2) {
    int t = blockIdx.x * blockDim.x + threadIdx.x;
    int node = t >> 4;
    if (node >= NN) return;
    const float* __restrict__ g = g_buf_agg;
    int lane = t & 15;
    int c = lane << 2;
    int start = csr_start(node);
    int n = g_deg_in[node];

    float4 a0 = make_float4(0.f, 0.f, 0.f, 0.f);
    float4 a1 = make_float4(0.f, 0.f, 0.f, 0.f);

    int j = 0;
    int end4 = n & ~3;
    for (; j < end4; j += 4) {
        int s0 = __ldg(&g_csr_src[start + j]);
        int s1 = __ldg(&g_csr_src[start + j + 1]);
        int s2 = __ldg(&g_csr_src[start + j + 2]);
        int s3 = __ldg(&g_csr_src[start + j + 3]);
        float4 v0 = *reinterpret_cast<const float4*>(g + (size_t)s0 * DC + c);
        float4 v1 = *reinterpret_cast<const float4*>(g + (size_t)s1 * DC + c);
        float4 v2 = *reinterpret_cast<const float4*>(g + (size_t)s2 * DC + c);
        float4 v3 = *reinterpret_cast<const float4*>(g + (size_t)s3 * DC + c);
        a0.x += v0.x + v2.x; a0.y += v0.y + v2.y;
        a0.z += v0.z + v2.z; a0.w += v0.w + v2.w;
        a1.x += v1.x + v3.x; a1.y += v1.y + v3.y;
        a1.z += v1.z + v3.z; a1.w += v1.w + v3.w;
    }
    for (; j < n; ++j) {
        int s0 = __ldg(&g_csr_src[start + j]);
        float4 v0 = *reinterpret_cast<const float4*>(g + (size_t)s0 * DC + c);
        a0.x += v0.x; a0.y += v0.y; a0.z += v0.z; a0.w += v0.w;
    }
    a0.x += a1.x; a0.y += a1.y; a0.z += a1.z; a0.w += a1.w;

    float nd = g_norm_dst[node];
    float4 b = *reinterpret_cast<const float4*>(b2 + c);
    a0.x = fmaf(a0.x, nd, b.x);
    a0.y = fmaf(a0.y, nd, b.y);
    a0.z = fmaf(a0.z, nd, b.z);
    a0.w = fmaf(a0.w, nd, b.w);
    *reinterpret_cast<float4*>(out + (size_t)node * DC + c) = a0;
}

// ---------------- fused GEMM (f32x2 packed inner loop, R10 layout) ------------
// XFORM: 0 none; 1 = (v - mean*ns[row]) * rstd   (layer-3 input, h pre-scaled)
// OUT_SCALE: multiply stored output by ns[row] (stats computed pre-scale)
// STATS: -1 none, 0 -> sum0, 1 -> sum1
template<int OUTW, int IN_SEL, int OUT_SEL, int XFORM, bool BIAS_RELU, bool OUT_SCALE, int STATS>
__global__ void __launch_bounds__(256) k_gemm(const float* __restrict__ W,
                                              const float* __restrict__ bias) {
    constexpr int CT = OUTW / 16;       // cols per thread (8 or 4)
    constexpr int CP = CT / 2;          // packed col-pairs per thread (4 or 2)
    __shared__ float As[64 * 132];

    const float* __restrict__ A = buf_sel(IN_SEL);
    float* __restrict__ out = buf_sel_w(OUT_SEL);

    int rowBase = blockIdx.x * 64;

    #pragma unroll
    for (int it = 0; it < 8; ++it) {
        int idx = threadIdx.x + it * 256;
        int r   = idx >> 5;
        int c   = (idx & 31) << 2;
        int row = rowBase + r;
        float4 v = make_float4(0.f, 0.f, 0.f, 0.f);
        if (row < NN) {
            v = *reinterpret_cast<const float4*>(A + (size_t)row * DIM + c);
            if (XFORM == 1) {
                float ns = g_norm_src[row];
                float4 m  = *reinterpret_cast<const float4*>(g_mean + c);
                float4 rs = *reinterpret_cast<const float4*>(g_rstd + c);
                v.x = (v.x - m.x * ns) * rs.x;
                v.y = (v.y - m.y * ns) * rs.y;
                v.z = (v.z - m.z * ns) * rs.z;
                v.w = (v.w - m.w * ns) * rs.w;
            }
        }
        *reinterpret_cast<float4*>(&As[r * 132 + c]) = v;
    }
    __syncthreads();

    int tr = threadIdx.x >> 4;
    int tc = threadIdx.x & 15;
    const float* A0 = &As[(tr * 4) * 132];

    u64 acc[4][CP];
    #pragma unroll
    for (int i = 0; i < 4; ++i)
        #pragma unroll
        for (int j = 0; j < CP; ++j) acc[i][j] = 0ull;

    const float* wbase = W + tc * CT;

    #pragma unroll 4
    for (int k = 0; k < 128; ++k) {
        u64 a0 = pack_dup(A0[k]);
        u64 a1 = pack_dup(A0[132 + k]);
        u64 a2 = pack_dup(A0[264 + k]);
        u64 a3 = pack_dup(A0[396 + k]);
        u64 w[CP];
        {
            const float* wrow = wbase + k * OUTW;
            asm("ld.global.nc.v2.u64 {%0, %1}, [%2];"
                : "=l"(w[0]), "=l"(w[1]) : "l"(wrow));
            if (CP == 4) {
                asm("ld.global.nc.v2.u64 {%0, %1}, [%2];"
                    : "=l"(w[2]), "=l"(w[3]) : "l"(wrow + 4));
            }
        }
        #pragma unroll
        for (int j = 0; j < CP; ++j) {
            FMA2(acc[0][j], a0, w[j]);
            FMA2(acc[1][j], a1, w[j]);
            FMA2(acc[2][j], a2, w[j]);
            FMA2(acc[3][j], a3, w[j]);
        }
    }

    // epilogue: unpack, bias+relu, store; keep values for stats
    float res[4][CT];
    float bv[CT];
    if (BIAS_RELU) {
        #pragma unroll
        for (int j0 = 0; j0 < CT; j0 += 4) {
            float4 b = __ldg(reinterpret_cast<const float4*>(bias + tc * CT + j0));
            bv[j0] = b.x; bv[j0 + 1] = b.y; bv[j0 + 2] = b.z; bv[j0 + 3] = b.w;
        }
    }
    #pragma unroll
    for (int i = 0; i < 4; ++i) {
        int row = rowBase + tr * 4 + i;
        bool valid = row < NN;
        #pragma unroll
        for (int j = 0; j < CP; ++j) {
            float lo, hi;
            unpack2(acc[i][j], lo, hi);
            if (BIAS_RELU) {
                lo = fmaxf(lo + bv[2 * j], 0.f);
                hi = fmaxf(hi + bv[2 * j + 1], 0.f);
            }
            res[i][2 * j]     = valid ? lo : 0.f;
            res[i][2 * j + 1] = valid ? hi : 0.f;
        }
        if (valid) {
            float osc = OUT_SCALE ? __ldg(&g_norm_src[row]) : 1.0f;
            #pragma unroll
            for (int j0 = 0; j0 < CT; j0 += 4) {
                float4 y4;
                y4.x = res[i][j0 + 0] * osc; y4.y = res[i][j0 + 1] * osc;
                y4.z = res[i][j0 + 2] * osc; y4.w = res[i][j0 + 3] * osc;
                *reinterpret_cast<float4*>(out + (size_t)row * OUTW + tc * CT + j0) = y4;
            }
        }
    }

    if (STATS >= 0) {
        float* SUM = (STATS == 0) ? g_sum0 : g_sum1;
        float* SQ  = (STATS == 0) ? g_sumsq0 : g_sumsq1;
        float* sh = As;
        __syncthreads();
        #pragma unroll
        for (int j = 0; j < CT; ++j) {
            float s = (res[0][j] + res[1][j]) + (res[2][j] + res[3][j]);
            float q = fmaf(res[0][j], res[0][j],
                      fmaf(res[1][j], res[1][j],
                      fmaf(res[2][j], res[2][j], res[3][j] * res[3][j])));
            int col = tc * CT + j;
            sh[tr * 128 + col] = s;
            sh[2048 + tr * 128 + col] = q;
        }
        __syncthreads();
        if (threadIdx.x < 128) {
            int col = threadIdx.x;
            float s = 0.f, q = 0.f;
            #pragma unroll
            for (int k2 = 0; k2 < 16; ++k2) {
                s += sh[k2 * 128 + col];
                q += sh[2048 + k2 * 128 + col];
            }
            atomicAdd(&SUM[col], s);
            atomicAdd(&SQ[col], q);
        }
    }
}

// ---------------- finalize BN stats (MUFU work lives here, 128 threads) -------
template<int L>
__global__ void k_finalize_stats() {
    int i = threadIdx.x;
    if (i < DIM) {
        const float* S = (L == 0) ? g_sum0 : g_sum1;
        const float* Q = (L == 0) ? g_sumsq0 : g_sumsq1;
        float inv = 1.0f / (float)NN;
        float mean = S[i] * inv;
        float var  = fmaxf(Q[i] * inv - mean * mean, 0.f);
        g_mean[i] = mean;
        g_rstd[i] = rsqrtf(var + BN_EPS);
    }
}

// ---------------- tail reset ----------------------------------------------------
__global__ void k_reset() {
    int i = blockIdx.x * blockDim.x + threadIdx.x;
    if (i < NN) {
        g_deg_out[i] = 0; g_deg_in[i] = 0; g_cursor[i] = 0;
    }
}

// ---------------- launch ---------------------------------------------------------
extern "C" void kernel_launch(void* const* d_in, const int* in_sizes, int n_in,
                              void* d_out, int out_size) {
    const float* features = (const float*)d_in[0];
    const float* W0 = (const float*)d_in[1];
    const float* b0 = (const float*)d_in[2];
    const float* W1 = (const float*)d_in[3];
    const float* b1 = (const float*)d_in[4];
    const float* W2 = (const float*)d_in[5];
    const float* b2 = (const float*)d_in[6];
    const int* src = (const int*)d_in[7];
    const int* dst = (const int*)d_in[8];
    float* out = (float*)d_out;

    const int TB = 256;
    const int gN      = (NN + TB - 1) / TB;
    const int gE      = (NE + TB - 1) / TB;
    const int gPull   = (NN * 32 + TB - 1) / TB;
    const int gPull64 = (NN * 16 + TB - 1) / TB;
    const int gGemm   = (NN + 63) / 64;

    // setup (counters arrive zeroed: zero-init first call, k_reset tail after)
    k_count<<<gE, TB>>>(src, dst);          // #1
    k_scan_norms<<<NB, SCAN_B>>>();         // #2
    k_scan_block<<<1, 128>>>();             // #3
    k_fill_csr<<<gE, TB>>>(src, dst);       // #4 (profiled slot)

    // layer 1: agg = nd * A~(ns*feat) (+ sns); h' = ns*relu(agg@W0+b0); stats->0
    k_pull128_l1<<<gPull, TB>>>(features);
    k_gemm<128, BUF_AGG, BUF_H, 0, true, true, 0><<<gGemm, TB>>>(W0, b0);
    k_finalize_stats<0><<<1, 128>>>();

    // layer 2: pure-sum pull with BN-fold epilogue; h' = ns*relu(...); stats->1
    k_pull128_fast<<<gPull, TB>>>();
    k_gemm<128, BUF_AGG, BUF_H, 0, true, true, 1><<<gGemm, TB>>>(W1, b1);
    k_finalize_stats<1><<<1, 128>>>();

    // layer 3: g = ((h' - m*ns)*rs) @ W2, then pure-sum pull + nd,b2 epilogue
    k_gemm<64, BUF_H, BUF_AGG, 1, false, false, -1><<<gGemm, TB>>>(W2, nullptr);
    k_pull64<<<gPull64, TB>>>(out, b2);

    // leave counters zeroed for next invocation
    k_reset<<<gN, TB>>>();
}

// round 13
// speedup vs baseline: 1.3039x; 1.0027x over previous
#include <cuda_runtime.h>

#define NN 100000
#define NE 1600000
#define DIM 128
#define DC 64
#define BN_EPS 1e-5f
#define SCAN_B 1024
#define NB ((NN + SCAN_B - 1) / SCAN_B)   // 98

// ---------------- f32x2 packed-math helpers ---------------------------------
typedef unsigned long long u64;

__device__ __forceinline__ u64 pack_dup(float v) {
    u64 r;
    asm("mov.b64 %0, {%1, %1};" : "=l"(r) : "f"(v));
    return r;
}
__device__ __forceinline__ void unpack2(u64 v, float& lo, float& hi) {
    asm("mov.b64 {%0, %1}, %2;" : "=f"(lo), "=f"(hi) : "l"(v));
}
#define FMA2(acc, a, b) \
    asm("fma.rn.f32x2 %0, %1, %2, %0;" : "+l"(acc) : "l"(a), "l"(b))

// ---------------- scratch (device globals; zero-initialized at load) -------
__device__ float g_buf_agg[NN * DIM];   // h2' (layer-2 output)
__device__ float g_buf_h[NN * DIM];     // h1' (layer-1 output), then g [N,64]
__device__ float g_norm_src[NN];
__device__ float g_norm_dst[NN];
__device__ float g_sns[NN];             // written by fused-L1 gather
__device__ int   g_deg_out[NN];         // reset tail
__device__ int   g_deg_in[NN];          // reset tail
__device__ int   g_off[NN];
__device__ int   g_blockoff[NB];
__device__ int   g_blocksum[NB];
__device__ int   g_cursor[NN];          // reset tail
__device__ int   g_csr_src[NE];
__device__ float g_sum0[DIM], g_sumsq0[DIM];
__device__ float g_sum1[DIM], g_sumsq1[DIM];
__device__ float g_mean[DIM], g_rstd[DIM];

__device__ __forceinline__ int csr_start(int node) {
    return g_off[node] + g_blockoff[node >> 10];
}

// ---------------- setup -------------------------------------------------------
__global__ void k_count(const int* __restrict__ src, const int* __restrict__ dst) {
    int e = blockIdx.x * blockDim.x + threadIdx.x;
    if (e < NE) {
        atomicAdd(&g_deg_out[src[e]], 1);
        atomicAdd(&g_deg_in[dst[e]], 1);
    }
}

__global__ void __launch_bounds__(SCAN_B) k_scan_norms() {
    __shared__ int s[SCAN_B];
    int i = blockIdx.x * SCAN_B + threadIdx.x;
    int din = (i < NN) ? g_deg_in[i] : 0;
    s[threadIdx.x] = din;
    __syncthreads();
    #pragma unroll
    for (int off = 1; off < SCAN_B; off <<= 1) {
        int v = (threadIdx.x >= off) ? s[threadIdx.x - off] : 0;
        __syncthreads();
        s[threadIdx.x] += v;
        __syncthreads();
    }
    if (i < NN) {
        g_off[i] = s[threadIdx.x] - din;
        g_norm_src[i] = rsqrtf(fmaxf((float)g_deg_out[i], 1.0f));
        g_norm_dst[i] = rsqrtf(fmaxf((float)din, 1.0f));
    }
    if (threadIdx.x == SCAN_B - 1) g_blocksum[blockIdx.x] = s[SCAN_B - 1];
    if (blockIdx.x == 0 && threadIdx.x < DIM) {
        g_sum0[threadIdx.x] = 0.f; g_sumsq0[threadIdx.x] = 0.f;
        g_sum1[threadIdx.x] = 0.f; g_sumsq1[threadIdx.x] = 0.f;
    }
}

__global__ void k_scan_block() {
    __shared__ int s[NB];
    if (threadIdx.x < NB) s[threadIdx.x] = g_blocksum[threadIdx.x];
    __syncthreads();
    if (threadIdx.x == 0) {
        int acc = 0;
        for (int b = 0; b < NB; ++b) { int v = s[b]; s[b] = acc; acc += v; }
    }
    __syncthreads();
    if (threadIdx.x < NB) g_blockoff[threadIdx.x] = s[threadIdx.x];
}

__global__ void k_fill_csr(const int* __restrict__ src, const int* __restrict__ dst) {
    int e = blockIdx.x * blockDim.x + threadIdx.x;
    if (e < NE) {
        int d = dst[e];
        int pos = atomicAdd(&g_cursor[d], 1);
        g_csr_src[g_off[d] + g_blockoff[d >> 10] + pos] = src[e];
    }
}

// ---------------- fused pull + GEMM (128-wide layers) --------------------------
// LAYER 0: gather ns-weighted features, agg *= nd; GEMM -> g_buf_h; stats->sum0
// LAYER 1: pure-sum gather of h1' (pre-scaled), BN-fold epilogue; GEMM -> g_buf_agg; stats->sum1
template<int LAYER>
__global__ void __launch_bounds__(256) k_fused128(const float* __restrict__ hext,
                                                  const float* __restrict__ W,
                                                  const float* __restrict__ bias) {
    __shared__ float As[64 * 132];

    const float* __restrict__ h = (LAYER == 0) ? hext : g_buf_h;
    float* __restrict__ out = (LAYER == 0) ? g_buf_h : g_buf_agg;

    int rowBase = blockIdx.x * 64;
    int wid  = threadIdx.x >> 5;
    int lane = threadIdx.x & 31;
    int c = lane << 2;

    // ---- gather phase: warp w aggregates nodes rowBase + w*8 .. +7 ----
    #pragma unroll 1
    for (int i = 0; i < 8; ++i) {
        int r = wid * 8 + i;
        int node = rowBase + r;
        float4 a0 = make_float4(0.f, 0.f, 0.f, 0.f);
        float4 a1 = make_float4(0.f, 0.f, 0.f, 0.f);
        if (node < NN) {
            int start = csr_start(node);
            int n = g_deg_in[node];
            float sns = 0.f;
            int j = 0;
            int end4 = n & ~3;
            for (; j < end4; j += 4) {
                int s0 = __ldg(&g_csr_src[start + j]);
                int s1 = __ldg(&g_csr_src[start + j + 1]);
                int s2 = __ldg(&g_csr_src[start + j + 2]);
                int s3 = __ldg(&g_csr_src[start + j + 3]);
                float4 v0 = *reinterpret_cast<const float4*>(h + (size_t)s0 * DIM + c);
                float4 v1 = *reinterpret_cast<const float4*>(h + (size_t)s1 * DIM + c);
                float4 v2 = *reinterpret_cast<const float4*>(h + (size_t)s2 * DIM + c);
                float4 v3 = *reinterpret_cast<const float4*>(h + (size_t)s3 * DIM + c);
                if (LAYER == 0) {
                    float n0 = __ldg(&g_norm_src[s0]);
                    float n1 = __ldg(&g_norm_src[s1]);
                    float n2 = __ldg(&g_norm_src[s2]);
                    float n3 = __ldg(&g_norm_src[s3]);
                    a0.x = fmaf(n0, v0.x, a0.x); a0.y = fmaf(n0, v0.y, a0.y);
                    a0.z = fmaf(n0, v0.z, a0.z); a0.w = fmaf(n0, v0.w, a0.w);
                    a1.x = fmaf(n1, v1.x, a1.x); a1.y = fmaf(n1, v1.y, a1.y);
                    a1.z = fmaf(n1, v1.z, a1.z); a1.w = fmaf(n1, v1.w, a1.w);
                    a0.x = fmaf(n2, v2.x, a0.x); a0.y = fmaf(n2, v2.y, a0.y);
                    a0.z = fmaf(n2, v2.z, a0.z); a0.w = fmaf(n2, v2.w, a0.w);
                    a1.x = fmaf(n3, v3.x, a1.x); a1.y = fmaf(n3, v3.y, a1.y);
                    a1.z = fmaf(n3, v3.z, a1.z); a1.w = fmaf(n3, v3.w, a1.w);
                    sns += (n0 + n1) + (n2 + n3);
                } else {
                    a0.x += v0.x + v2.x; a0.y += v0.y + v2.y;
                    a0.z += v0.z + v2.z; a0.w += v0.w + v2.w;
                    a1.x += v1.x + v3.x; a1.y += v1.y + v3.y;
                    a1.z += v1.z + v3.z; a1.w += v1.w + v3.w;
                }
            }
            for (; j < n; ++j) {
                int s0 = __ldg(&g_csr_src[start + j]);
                float4 v0 = *reinterpret_cast<const float4*>(h + (size_t)s0 * DIM + c);
                if (LAYER == 0) {
                    float n0 = __ldg(&g_norm_src[s0]);
                    a0.x = fmaf(n0, v0.x, a0.x); a0.y = fmaf(n0, v0.y, a0.y);
                    a0.z = fmaf(n0, v0.z, a0.z); a0.w = fmaf(n0, v0.w, a0.w);
                    sns += n0;
                } else {
                    a0.x += v0.x; a0.y += v0.y; a0.z += v0.z; a0.w += v0.w;
                }
            }
            a0.x += a1.x; a0.y += a1.y; a0.z += a1.z; a0.w += a1.w;

            float nd = g_norm_dst[node];
            if (LAYER == 0) {
                a0.x *= nd; a0.y *= nd; a0.z *= nd; a0.w *= nd;
                if (lane == 0) g_sns[node] = sns;
            } else {
                float snv = __ldg(&g_sns[node]);
                float4 m  = *reinterpret_cast<const float4*>(g_mean + c);
                float4 rs = *reinterpret_cast<const float4*>(g_rstd + c);
                a0.x = (a0.x - m.x * snv) * rs.x * nd;
                a0.y = (a0.y - m.y * snv) * rs.y * nd;
                a0.z = (a0.z - m.z * snv) * rs.z * nd;
                a0.w = (a0.w - m.w * snv) * rs.w * nd;
            }
        }
        *reinterpret_cast<float4*>(&As[r * 132 + c]) = a0;
    }
    __syncthreads();

    // ---- GEMM phase (proven R10 f32x2 loop, OUTW=128) ----
    constexpr int CT = 8;
    constexpr int CP = 4;
    int tr = threadIdx.x >> 4;
    int tc = threadIdx.x & 15;
    const float* A0 = &As[(tr * 4) * 132];

    u64 acc[4][CP];
    #pragma unroll
    for (int i = 0; i < 4; ++i)
        #pragma unroll
        for (int j = 0; j < CP; ++j) acc[i][j] = 0ull;

    const float* wbase = W + tc * CT;

    #pragma unroll 4
    for (int k = 0; k < 128; ++k) {
        u64 a0 = pack_dup(A0[k]);
        u64 a1 = pack_dup(A0[132 + k]);
        u64 a2 = pack_dup(A0[264 + k]);
        u64 a3 = pack_dup(A0[396 + k]);
        u64 w[CP];
        {
            const float* wrow = wbase + k * DIM;
            asm("ld.global.nc.v2.u64 {%0, %1}, [%2];"
                : "=l"(w[0]), "=l"(w[1]) : "l"(wrow));
            asm("ld.global.nc.v2.u64 {%0, %1}, [%2];"
                : "=l"(w[2]), "=l"(w[3]) : "l"(wrow + 4));
        }
        #pragma unroll
        for (int j = 0; j < CP; ++j) {
            FMA2(acc[0][j], a0, w[j]);
            FMA2(acc[1][j], a1, w[j]);
            FMA2(acc[2][j], a2, w[j]);
            FMA2(acc[3][j], a3, w[j]);
        }
    }

    // epilogue: unpack, bias+relu, *ns store; keep pre-scale values for stats
    float res[4][CT];
    float bv[CT];
    #pragma unroll
    for (int j0 = 0; j0 < CT; j0 += 4) {
        float4 b = __ldg(reinterpret_cast<const float4*>(bias + tc * CT + j0));
        bv[j0] = b.x; bv[j0 + 1] = b.y; bv[j0 + 2] = b.z; bv[j0 + 3] = b.w;
    }
    #pragma unroll
    for (int i = 0; i < 4; ++i) {
        int row = rowBase + tr * 4 + i;
        bool valid = row < NN;
        #pragma unroll
        for (int j = 0; j < CP; ++j) {
            float lo, hi;
            unpack2(acc[i][j], lo, hi);
            lo = fmaxf(lo + bv[2 * j], 0.f);
            hi = fmaxf(hi + bv[2 * j + 1], 0.f);
            res[i][2 * j]     = valid ? lo : 0.f;
            res[i][2 * j + 1] = valid ? hi : 0.f;
        }
        if (valid) {
            float osc = __ldg(&g_norm_src[row]);
            #pragma unroll
            for (int j0 = 0; j0 < CT; j0 += 4) {
                float4 y4;
                y4.x = res[i][j0 + 0] * osc; y4.y = res[i][j0 + 1] * osc;
                y4.z = res[i][j0 + 2] * osc; y4.w = res[i][j0 + 3] * osc;
                *reinterpret_cast<float4*>(out + (size_t)row * DIM + tc * CT + j0) = y4;
            }
        }
    }

    // BN stats reduction into sum{LAYER}
    {
        float* SUM = (LAYER == 0) ? g_sum0 : g_sum1;
        float* SQ  = (LAYER == 0) ? g_sumsq0 : g_sumsq1;
        float* sh = As;
        __syncthreads();
        #pragma unroll
        for (int j = 0; j < CT; ++j) {
            float s = (res[0][j] + res[1][j]) + (res[2][j] + res[3][j]);
            float q = fmaf(res[0][j], res[0][j],
                      fmaf(res[1][j], res[1][j],
                      fmaf(res[2][j], res[2][j], res[3][j] * res[3][j])));
            int col = tc * CT + j;
            sh[tr * 128 + col] = s;
            sh[2048 + tr * 128 + col] = q;
        }
        __syncthreads();
        if (threadIdx.x < 128) {
            int col = threadIdx.x;
            float s = 0.f, q = 0.f;
            #pragma unroll
            for (int k2 = 0; k2 < 16; ++k2) {
                s += sh[k2 * 128 + col];
                q += sh[2048 + k2 * 128 + col];
            }
            atomicAdd(&SUM[col], s);
            atomicAdd(&SQ[col], q);
        }
    }
}

// ---------------- layer-3 GEMM: g = ((h2' - m*ns)*rs) @ W2  (64-wide out) -----
__global__ void __launch_bounds__(256) k_gemm64(const float* __restrict__ W) {
    constexpr int CT = 4;
    constexpr int CP = 2;
    __shared__ float As[64 * 132];

    const float* __restrict__ A = g_buf_agg;
    float* __restrict__ out = g_buf_h;

    int rowBase = blockIdx.x * 64;

    #pragma unroll
    for (int it = 0; it < 8; ++it) {
        int idx = threadIdx.x + it * 256;
        int r   = idx >> 5;
        int c   = (idx & 31) << 2;
        int row = rowBase + r;
        float4 v = make_float4(0.f, 0.f, 0.f, 0.f);
        if (row < NN) {
            v = *reinterpret_cast<const float4*>(A + (size_t)row * DIM + c);
            float ns = g_norm_src[row];
            float4 m  = *reinterpret_cast<const float4*>(g_mean + c);
            float4 rs = *reinterpret_cast<const float4*>(g_rstd + c);
            v.x = (v.x - m.x * ns) * rs.x;
            v.y = (v.y - m.y * ns) * rs.y;
            v.z = (v.z - m.z * ns) * rs.z;
            v.w = (v.w - m.w * ns) * rs.w;
        }
        *reinterpret_cast<float4*>(&As[r * 132 + c]) = v;
    }
    __syncthreads();

    int tr = threadIdx.x >> 4;
    int tc = threadIdx.x & 15;
    const float* A0 = &As[(tr * 4) * 132];

    u64 acc[4][CP];
    #pragma unroll
    for (int i = 0; i < 4; ++i)
        #pragma unroll
        for (int j = 0; j < CP; ++j) acc[i][j] = 0ull;

    const float* wbase = W + tc * CT;

    #pragma unroll 4
    for (int k = 0; k < 128; ++k) {
        u64 a0 = pack_dup(A0[k]);
        u64 a1 = pack_dup(A0[132 + k]);
        u64 a2 = pack_dup(A0[264 + k]);
        u64 a3 = pack_dup(A0[396 + k]);
        u64 w[CP];
        asm("ld.global.nc.v2.u64 {%0, %1}, [%2];"
            : "=l"(w[0]), "=l"(w[1]) : "l"(wbase + k * DC));
        #pragma unroll
        for (int j = 0; j < CP; ++j) {
            FMA2(acc[0][j], a0, w[j]);
            FMA2(acc[1][j], a1, w[j]);
            FMA2(acc[2][j], a2, w[j]);
            FMA2(acc[3][j], a3, w[j]);
        }
    }

    #pragma unroll
    for (int i = 0; i < 4; ++i) {
        int row = rowBase + tr * 4 + i;
        if (row >= NN) continue;
        float4 y4;
        float lo, hi;
        unpack2(acc[i][0], lo, hi); y4.x = lo; y4.y = hi;
        unpack2(acc[i][1], lo, hi); y4.z = lo; y4.w = hi;
        *reinterpret_cast<float4*>(out + (size_t)row * DC + tc * CT) = y4;
    }
}

// ---------------- pull, final layer (64 wide) ---------------------------------
__global__ void __launch_bounds__(256) k_pull64(float* __restrict__ out,
                                                const float* __restrict__ b2) {
    int t = blockIdx.x * blockDim.x + threadIdx.x;
    int node = t >> 4;
    if (node >= NN) return;
    const float* __restrict__ g = g_buf_h;
    int lane = t & 15;
    int c = lane << 2;
    int start = csr_start(node);
    int n = g_deg_in[node];

    float4 a0 = make_float4(0.f, 0.f, 0.f, 0.f);
    float4 a1 = make_float4(0.f, 0.f, 0.f, 0.f);

    int j = 0;
    int end4 = n & ~3;
    for (; j < end4; j += 4) {
        int s0 = __ldg(&g_csr_src[start + j]);
        int s1 = __ldg(&g_csr_src[start + j + 1]);
        int s2 = __ldg(&g_csr_src[start + j + 2]);
        int s3 = __ldg(&g_csr_src[start + j + 3]);
        float4 v0 = *reinterpret_cast<const float4*>(g + (size_t)s0 * DC + c);
        float4 v1 = *reinterpret_cast<const float4*>(g + (size_t)s1 * DC + c);
        float4 v2 = *reinterpret_cast<const float4*>(g + (size_t)s2 * DC + c);
        float4 v3 = *reinterpret_cast<const float4*>(g + (size_t)s3 * DC + c);
        a0.x += v0.x + v2.x; a0.y += v0.y + v2.y;
        a0.z += v0.z + v2.z; a0.w += v0.w + v2.w;
        a1.x += v1.x + v3.x; a1.y += v1.y + v3.y;
        a1.z += v1.z + v3.z; a1.w += v1.w + v3.w;
    }
    for (; j < n; ++j) {
        int s0 = __ldg(&g_csr_src[start + j]);
        float4 v0 = *reinterpret_cast<const float4*>(g + (size_t)s0 * DC + c);
        a0.x += v0.x; a0.y += v0.y; a0.z += v0.z; a0.w += v0.w;
    }
    a0.x += a1.x; a0.y += a1.y; a0.z += a1.z; a0.w += a1.w;

    float nd = g_norm_dst[node];
    float4 b = *reinterpret_cast<const float4*>(b2 + c);
    a0.x = fmaf(a0.x, nd, b.x);
    a0.y = fmaf(a0.y, nd, b.y);
    a0.z = fmaf(a0.z, nd, b.z);
    a0.w = fmaf(a0.w, nd, b.w);
    *reinterpret_cast<float4*>(out + (size_t)node * DC + c) = a0;
}

// ---------------- finalize BN stats -------------------------------------------
template<int L>
__global__ void k_finalize_stats() {
    int i = threadIdx.x;
    if (i < DIM) {
        const float* S = (L == 0) ? g_sum0 : g_sum1;
        const float* Q = (L == 0) ? g_sumsq0 : g_sumsq1;
        float inv = 1.0f / (float)NN;
        float mean = S[i] * inv;
        float var  = fmaxf(Q[i] * inv - mean * mean, 0.f);
        g_mean[i] = mean;
        g_rstd[i] = rsqrtf(var + BN_EPS);
    }
}

// ---------------- tail reset ----------------------------------------------------
__global__ void k_reset() {
    int i = blockIdx.x * blockDim.x + threadIdx.x;
    if (i < NN) {
        g_deg_out[i] = 0; g_deg_in[i] = 0; g_cursor[i] = 0;
    }
}

// ---------------- launch ---------------------------------------------------------
extern "C" void kernel_launch(void* const* d_in, const int* in_sizes, int n_in,
                              void* d_out, int out_size) {
    const float* features = (const float*)d_in[0];
    const float* W0 = (const float*)d_in[1];
    const float* b0 = (const float*)d_in[2];
    const float* W1 = (const float*)d_in[3];
    const float* b1 = (const float*)d_in[4];
    const float* W2 = (const float*)d_in[5];
    const float* b2 = (const float*)d_in[6];
    const int* src = (const int*)d_in[7];
    const int* dst = (const int*)d_in[8];
    float* out = (float*)d_out;

    const int TB = 256;
    const int gN      = (NN + TB - 1) / TB;
    const int gE      = (NE + TB - 1) / TB;
    const int gPull64 = (NN * 16 + TB - 1) / TB;
    const int gGemm   = (NN + 63) / 64;

    // setup (counters arrive zeroed: zero-init first call, k_reset tail after)
    k_count<<<gE, TB>>>(src, dst);          // #1
    k_scan_norms<<<NB, SCAN_B>>>();         // #2
    k_scan_block<<<1, 128>>>();             // #3
    k_fill_csr<<<gE, TB>>>(src, dst);       // #4 (profiled slot)

    // layer 1 (fused pull+GEMM): features -> h1' in g_buf_h; stats->sum0
    k_fused128<0><<<gGemm, TB>>>(features, W0, b0);
    k_finalize_stats<0><<<1, 128>>>();

    // layer 2 (fused pull+GEMM): g_buf_h -> h2' in g_buf_agg; stats->sum1
    k_fused128<1><<<gGemm, TB>>>(nullptr, W1, b1);
    k_finalize_stats<1><<<1, 128>>>();

    // layer 3: g = ((h2' - m*ns)*rs) @ W2 -> g_buf_h, then pull64 + nd,b2
    k_gemm64<<<gGemm, TB>>>(W2);
    k_pull64<<<gPull64, TB>>>(out, b2);

    // leave counters zeroed for next invocation
    k_reset<<<gN, TB>>>();
}

// round 15
// speedup vs baseline: 1.3969x; 1.0713x over previous
#include <cuda_runtime.h>
#include <cuda_fp16.h>
#include <cstdint>

#define NN 100000
#define NE 1600000
#define DIM 128
#define DC 64
#define BN_EPS 1e-5f
#define SCAN_B 1024
#define NB ((NN + SCAN_B - 1) / SCAN_B)   // 98

// ---------------- f32x2 packed-math helpers ---------------------------------
typedef unsigned long long u64;
typedef unsigned int u32;

__device__ __forceinline__ u64 pack_dup(float v) {
    u64 r;
    asm("mov.b64 %0, {%1, %1};" : "=l"(r) : "f"(v));
    return r;
}
__device__ __forceinline__ void unpack2(u64 v, float& lo, float& hi) {
    asm("mov.b64 {%0, %1}, %2;" : "=f"(lo), "=f"(hi) : "l"(v));
}
#define FMA2(acc, a, b) \
    asm("fma.rn.f32x2 %0, %1, %2, %0;" : "+l"(acc) : "l"(a), "l"(b))

// ---------------- fp16 load/store helpers (fp32 math, fp16 storage) ---------
__device__ __forceinline__ float4 ldg_h4(const __half* p) {
    uint2 u = __ldg(reinterpret_cast<const uint2*>(p));
    __half2 h0 = *reinterpret_cast<__half2*>(&u.x);
    __half2 h1 = *reinterpret_cast<__half2*>(&u.y);
    float2 f0 = __half22float2(h0);
    float2 f1 = __half22float2(h1);
    return make_float4(f0.x, f0.y, f1.x, f1.y);
}
__device__ __forceinline__ void st_h4(__half* p, float x, float y, float z, float w) {
    __half2 h0 = __floats2half2_rn(x, y);
    __half2 h1 = __floats2half2_rn(z, w);
    uint2 u;
    u.x = *reinterpret_cast<u32*>(&h0);
    u.y = *reinterpret_cast<u32*>(&h1);
    *reinterpret_cast<uint2*>(p) = u;
}

// ---------------- scratch (device globals; zero-initialized at load) -------
__device__ __align__(16) __half g_feat16[NN * DIM];  // fp16 features
__device__ __align__(16) __half g_h1[NN * DIM];      // h1' = ns*relu(...) fp16
__device__ __align__(16) __half g_h2[NN * DIM];      // h2' fp16
__device__ __align__(16) __half g_g16[NN * DC];      // layer-3 g fp16
__device__ float g_norm_src[NN];
__device__ float g_norm_dst[NN];
__device__ float g_sns[NN];
__device__ int   g_deg_out[NN];         // reset tail
__device__ int   g_deg_in[NN];          // reset tail
__device__ int   g_off[NN];
__device__ int   g_blockoff[NB];
__device__ int   g_blocksum[NB];
__device__ int   g_cursor[NN];          // reset tail
__device__ int   g_csr_src[NE];
__device__ float g_sum0[DIM], g_sumsq0[DIM];
__device__ float g_sum1[DIM], g_sumsq1[DIM];
__device__ float g_mean[DIM], g_rstd[DIM];

__device__ __forceinline__ int csr_start(int node) {
    return g_off[node] + g_blockoff[node >> 10];
}

// ---------------- setup -------------------------------------------------------
__global__ void k_count(const int* __restrict__ src, const int* __restrict__ dst) {
    int e = blockIdx.x * blockDim.x + threadIdx.x;
    if (e < NE) {
        atomicAdd(&g_deg_out[src[e]], 1);
        atomicAdd(&g_deg_in[dst[e]], 1);
    }
}

__global__ void __launch_bounds__(SCAN_B) k_scan_norms() {
    __shared__ int s[SCAN_B];
    int i = blockIdx.x * SCAN_B + threadIdx.x;
    int din = (i < NN) ? g_deg_in[i] : 0;
    s[threadIdx.x] = din;
    __syncthreads();
    #pragma unroll
    for (int off = 1; off < SCAN_B; off <<= 1) {
        int v = (threadIdx.x >= off) ? s[threadIdx.x - off] : 0;
        __syncthreads();
        s[threadIdx.x] += v;
        __syncthreads();
    }
    if (i < NN) {
        g_off[i] = s[threadIdx.x] - din;
        g_norm_src[i] = rsqrtf(fmaxf((float)g_deg_out[i], 1.0f));
        g_norm_dst[i] = rsqrtf(fmaxf((float)din, 1.0f));
    }
    if (threadIdx.x == SCAN_B - 1) g_blocksum[blockIdx.x] = s[SCAN_B - 1];
    if (blockIdx.x == 0 && threadIdx.x < DIM) {
        g_sum0[threadIdx.x] = 0.f; g_sumsq0[threadIdx.x] = 0.f;
        g_sum1[threadIdx.x] = 0.f; g_sumsq1[threadIdx.x] = 0.f;
    }
}

__global__ void k_scan_block() {
    __shared__ int s[NB];
    if (threadIdx.x < NB) s[threadIdx.x] = g_blocksum[threadIdx.x];
    __syncthreads();
    if (threadIdx.x == 0) {
        int acc = 0;
        for (int b = 0; b < NB; ++b) { int v = s[b]; s[b] = acc; acc += v; }
    }
    __syncthreads();
    if (threadIdx.x < NB) g_blockoff[threadIdx.x] = s[threadIdx.x];
}

__global__ void k_fill_csr(const int* __restrict__ src, const int* __restrict__ dst) {
    int e = blockIdx.x * blockDim.x + threadIdx.x;
    if (e < NE) {
        int d = dst[e];
        int pos = atomicAdd(&g_cursor[d], 1);
        g_csr_src[g_off[d] + g_blockoff[d >> 10] + pos] = src[e];
    }
}

// features -> fp16
__global__ void k_feat2h(const float* __restrict__ f) {
    int i = blockIdx.x * blockDim.x + threadIdx.x;    // over NN*DIM/4
    if (i < NN * DIM / 4) {
        float4 v = reinterpret_cast<const float4*>(f)[i];
        st_h4(&g_feat16[(size_t)i * 4], v.x, v.y, v.z, v.w);
    }
}

// ---------------- fused pull + GEMM (128-wide layers) --------------------------
// LAYER 0: gather ns*feat16, *nd; GEMM W0 -> h1' (fp16); stats->sum0; emits sns
// LAYER 1: pure-sum gather of h1' fp16, BN-fold; GEMM W1 -> h2' (fp16); stats->sum1
template<int LAYER>
__global__ void __launch_bounds__(256) k_fused128(const float* __restrict__ W,
                                                  const float* __restrict__ bias) {
    __shared__ float As[64 * 132];

    const __half* __restrict__ h = (LAYER == 0) ? g_feat16 : g_h1;
    __half* __restrict__ out = (LAYER == 0) ? g_h1 : g_h2;

    int rowBase = blockIdx.x * 64;
    int wid  = threadIdx.x >> 5;
    int lane = threadIdx.x & 31;
    int c = lane << 2;

    // ---- gather phase: warp w aggregates nodes rowBase + w*8 .. +7 ----
    #pragma unroll 1
    for (int i = 0; i < 8; ++i) {
        int r = wid * 8 + i;
        int node = rowBase + r;
        float4 a0 = make_float4(0.f, 0.f, 0.f, 0.f);
        float4 a1 = make_float4(0.f, 0.f, 0.f, 0.f);
        if (node < NN) {
            int start = csr_start(node);
            int n = g_deg_in[node];
            float sns = 0.f;
            int j = 0;
            int end4 = n & ~3;
            for (; j < end4; j += 4) {
                int s0 = __ldg(&g_csr_src[start + j]);
                int s1 = __ldg(&g_csr_src[start + j + 1]);
                int s2 = __ldg(&g_csr_src[start + j + 2]);
                int s3 = __ldg(&g_csr_src[start + j + 3]);
                float4 v0 = ldg_h4(h + (size_t)s0 * DIM + c);
                float4 v1 = ldg_h4(h + (size_t)s1 * DIM + c);
                float4 v2 = ldg_h4(h + (size_t)s2 * DIM + c);
                float4 v3 = ldg_h4(h + (size_t)s3 * DIM + c);
                if (LAYER == 0) {
                    float n0 = __ldg(&g_norm_src[s0]);
                    float n1 = __ldg(&g_norm_src[s1]);
                    float n2 = __ldg(&g_norm_src[s2]);
                    float n3 = __ldg(&g_norm_src[s3]);
                    a0.x = fmaf(n0, v0.x, a0.x); a0.y = fmaf(n0, v0.y, a0.y);
                    a0.z = fmaf(n0, v0.z, a0.z); a0.w = fmaf(n0, v0.w, a0.w);
                    a1.x = fmaf(n1, v1.x, a1.x); a1.y = fmaf(n1, v1.y, a1.y);
                    a1.z = fmaf(n1, v1.z, a1.z); a1.w = fmaf(n1, v1.w, a1.w);
                    a0.x = fmaf(n2, v2.x, a0.x); a0.y = fmaf(n2, v2.y, a0.y);
                    a0.z = fmaf(n2, v2.z, a0.z); a0.w = fmaf(n2, v2.w, a0.w);
                    a1.x = fmaf(n3, v3.x, a1.x); a1.y = fmaf(n3, v3.y, a1.y);
                    a1.z = fmaf(n3, v3.z, a1.z); a1.w = fmaf(n3, v3.w, a1.w);
                    sns += (n0 + n1) + (n2 + n3);
                } else {
                    a0.x += v0.x + v2.x; a0.y += v0.y + v2.y;
                    a0.z += v0.z + v2.z; a0.w += v0.w + v2.w;
                    a1.x += v1.x + v3.x; a1.y += v1.y + v3.y;
                    a1.z += v1.z + v3.z; a1.w += v1.w + v3.w;
                }
            }
            for (; j < n; ++j) {
                int s0 = __ldg(&g_csr_src[start + j]);
                float4 v0 = ldg_h4(h + (size_t)s0 * DIM + c);
                if (LAYER == 0) {
                    float n0 = __ldg(&g_norm_src[s0]);
                    a0.x = fmaf(n0, v0.x, a0.x); a0.y = fmaf(n0, v0.y, a0.y);
                    a0.z = fmaf(n0, v0.z, a0.z); a0.w = fmaf(n0, v0.w, a0.w);
                    sns += n0;
                } else {
                    a0.x += v0.x; a0.y += v0.y; a0.z += v0.z; a0.w += v0.w;
                }
            }
            a0.x += a1.x; a0.y += a1.y; a0.z += a1.z; a0.w += a1.w;

            float nd = g_norm_dst[node];
            if (LAYER == 0) {
                a0.x *= nd; a0.y *= nd; a0.z *= nd; a0.w *= nd;
                if (lane == 0) g_sns[node] = sns;
            } else {
                float snv = __ldg(&g_sns[node]);
                float4 m  = *reinterpret_cast<const float4*>(g_mean + c);
                float4 rs = *reinterpret_cast<const float4*>(g_rstd + c);
                a0.x = (a0.x - m.x * snv) * rs.x * nd;
                a0.y = (a0.y - m.y * snv) * rs.y * nd;
                a0.z = (a0.z - m.z * snv) * rs.z * nd;
                a0.w = (a0.w - m.w * snv) * rs.w * nd;
            }
        }
        *reinterpret_cast<float4*>(&As[r * 132 + c]) = a0;
    }
    __syncthreads();

    // ---- GEMM phase (f32x2, OUTW=128) ----
    constexpr int CT = 8;
    constexpr int CP = 4;
    int tr = threadIdx.x >> 4;
    int tc = threadIdx.x & 15;
    const float* A0 = &As[(tr * 4) * 132];

    u64 acc[4][CP];
    #pragma unroll
    for (int i = 0; i < 4; ++i)
        #pragma unroll
        for (int j = 0; j < CP; ++j) acc[i][j] = 0ull;

    const float* wbase = W + tc * CT;

    #pragma unroll 4
    for (int k = 0; k < 128; ++k) {
        u64 a0 = pack_dup(A0[k]);
        u64 a1 = pack_dup(A0[132 + k]);
        u64 a2 = pack_dup(A0[264 + k]);
        u64 a3 = pack_dup(A0[396 + k]);
        u64 w[CP];
        {
            const float* wrow = wbase + k * DIM;
            asm("ld.global.nc.v2.u64 {%0, %1}, [%2];"
                : "=l"(w[0]), "=l"(w[1]) : "l"(wrow));
            asm("ld.global.nc.v2.u64 {%0, %1}, [%2];"
                : "=l"(w[2]), "=l"(w[3]) : "l"(wrow + 4));
        }
        #pragma unroll
        for (int j = 0; j < CP; ++j) {
            FMA2(acc[0][j], a0, w[j]);
            FMA2(acc[1][j], a1, w[j]);
            FMA2(acc[2][j], a2, w[j]);
            FMA2(acc[3][j], a3, w[j]);
        }
    }

    // epilogue: unpack, bias+relu; store fp16 h' = osc*res; keep fp32 res for stats
    float res[4][CT];
    float bv[CT];
    #pragma unroll
    for (int j0 = 0; j0 < CT; j0 += 4) {
        float4 b = __ldg(reinterpret_cast<const float4*>(bias + tc * CT + j0));
        bv[j0] = b.x; bv[j0 + 1] = b.y; bv[j0 + 2] = b.z; bv[j0 + 3] = b.w;
    }
    #pragma unroll
    for (int i = 0; i < 4; ++i) {
        int row = rowBase + tr * 4 + i;
        bool valid = row < NN;
        #pragma unroll
        for (int j = 0; j < CP; ++j) {
            float lo, hi;
            unpack2(acc[i][j], lo, hi);
            lo = fmaxf(lo + bv[2 * j], 0.f);
            hi = fmaxf(hi + bv[2 * j + 1], 0.f);
            res[i][2 * j]     = valid ? lo : 0.f;
            res[i][2 * j + 1] = valid ? hi : 0.f;
        }
        if (valid) {
            float osc = __ldg(&g_norm_src[row]);
            __half* orow = out + (size_t)row * DIM + tc * CT;
            st_h4(orow,     res[i][0] * osc, res[i][1] * osc,
                            res[i][2] * osc, res[i][3] * osc);
            st_h4(orow + 4, res[i][4] * osc, res[i][5] * osc,
                            res[i][6] * osc, res[i][7] * osc);
        }
    }

    // BN stats reduction into sum{LAYER}
    {
        float* SUM = (LAYER == 0) ? g_sum0 : g_sum1;
        float* SQ  = (LAYER == 0) ? g_sumsq0 : g_sumsq1;
        float* sh = As;
        __syncthreads();
        #pragma unroll
        for (int j = 0; j < CT; ++j) {
            float s = (res[0][j] + res[1][j]) + (res[2][j] + res[3][j]);
            float q = fmaf(res[0][j], res[0][j],
                      fmaf(res[1][j], res[1][j],
                      fmaf(res[2][j], res[2][j], res[3][j] * res[3][j])));
            int col = tc * CT + j;
            sh[tr * 128 + col] = s;
            sh[2048 + tr * 128 + col] = q;
        }
        __syncthreads();
        if (threadIdx.x < 128) {
            int col = threadIdx.x;
            float s = 0.f, q = 0.f;
            #pragma unroll
            for (int k2 = 0; k2 < 16; ++k2) {
                s += sh[k2 * 128 + col];
                q += sh[2048 + k2 * 128 + col];
            }
            atomicAdd(&SUM[col], s);
            atomicAdd(&SQ[col], q);
        }
    }
}

// ---------------- layer-3 GEMM: g = ((h2' - m*ns)*rs) @ W2 -> fp16 g ----------
__global__ void __launch_bounds__(256) k_gemm64(const float* __restrict__ W) {
    constexpr int CP = 2;
    constexpr int CT = 4;
    __shared__ float As[64 * 132];

    int rowBase = blockIdx.x * 64;

    #pragma unroll
    for (int it = 0; it < 8; ++it) {
        int idx = threadIdx.x + it * 256;
        int r   = idx >> 5;
        int c   = (idx & 31) << 2;
        int row = rowBase + r;
        float4 v = make_float4(0.f, 0.f, 0.f, 0.f);
        if (row < NN) {
            v = ldg_h4(g_h2 + (size_t)row * DIM + c);
            float ns = g_norm_src[row];
            float4 m  = *reinterpret_cast<const float4*>(g_mean + c);
            float4 rs = *reinterpret_cast<const float4*>(g_rstd + c);
            v.x = (v.x - m.x * ns) * rs.x;
            v.y = (v.y - m.y * ns) * rs.y;
            v.z = (v.z - m.z * ns) * rs.z;
            v.w = (v.w - m.w * ns) * rs.w;
        }
        *reinterpret_cast<float4*>(&As[r * 132 + c]) = v;
    }
    __syncthreads();

    int tr = threadIdx.x >> 4;
    int tc = threadIdx.x & 15;
    const float* A0 = &As[(tr * 4) * 132];

    u64 acc[4][CP];
    #pragma unroll
    for (int i = 0; i < 4; ++i)
        #pragma unroll
        for (int j = 0; j < CP; ++j) acc[i][j] = 0ull;

    const float* wbase = W + tc * CT;

    #pragma unroll 4
    for (int k = 0; k < 128; ++k) {
        u64 a0 = pack_dup(A0[k]);
        u64 a1 = pack_dup(A0[132 + k]);
        u64 a2 = pack_dup(A0[264 + k]);
        u64 a3 = pack_dup(A0[396 + k]);
        u64 w[CP];
        asm("ld.global.nc.v2.u64 {%0, %1}, [%2];"
            : "=l"(w[0]), "=l"(w[1]) : "l"(wbase + k * DC));
        #pragma unroll
        for (int j = 0; j < CP; ++j) {
            FMA2(acc[0][j], a0, w[j]);
            FMA2(acc[1][j], a1, w[j]);
            FMA2(acc[2][j], a2, w[j]);
            FMA2(acc[3][j], a3, w[j]);
        }
    }

    #pragma unroll
    for (int i = 0; i < 4; ++i) {
        int row = rowBase + tr * 4 + i;
        if (row >= NN) continue;
        float x, y, z, w2;
        unpack2(acc[i][0], x, y);
        unpack2(acc[i][1], z, w2);
        st_h4(g_g16 + (size_t)row * DC + tc * CT, x, y, z, w2);
    }
}

// ---------------- pull, final layer (64 wide, fp16 gather, fp32 out) ----------
__global__ void __launch_bounds__(256) k_pull64(float* __restrict__ out,
                                                const float* __restrict__ b2) {
    int t = blockIdx.x * blockDim.x + threadIdx.x;
    int node = t >> 4;
    if (node >= NN) return;
    int lane = t & 15;
    int c = lane << 2;
    int start = csr_start(node);
    int n = g_deg_in[node];

    float4 a0 = make_float4(0.f, 0.f, 0.f, 0.f);
    float4 a1 = make_float4(0.f, 0.f, 0.f, 0.f);

    int j = 0;
    int end4 = n & ~3;
    for (; j < end4; j += 4) {
        int s0 = __ldg(&g_csr_src[start + j]);
        int s1 = __ldg(&g_csr_src[start + j + 1]);
        int s2 = __ldg(&g_csr_src[start + j + 2]);
        int s3 = __ldg(&g_csr_src[start + j + 3]);
        float4 v0 = ldg_h4(g_g16 + (size_t)s0 * DC + c);
        float4 v1 = ldg_h4(g_g16 + (size_t)s1 * DC + c);
        float4 v2 = ldg_h4(g_g16 + (size_t)s2 * DC + c);
        float4 v3 = ldg_h4(g_g16 + (size_t)s3 * DC + c);
        a0.x += v0.x + v2.x; a0.y += v0.y + v2.y;
        a0.z += v0.z + v2.z; a0.w += v0.w + v2.w;
        a1.x += v1.x + v3.x; a1.y += v1.y + v3.y;
        a1.z += v1.z + v3.z; a1.w += v1.w + v3.w;
    }
    for (; j < n; ++j) {
        int s0 = __ldg(&g_csr_src[start + j]);
        float4 v0 = ldg_h4(g_g16 + (size_t)s0 * DC + c);
        a0.x += v0.x; a0.y += v0.y; a0.z += v0.z; a0.w += v0.w;
    }
    a0.x += a1.x; a0.y += a1.y; a0.z += a1.z; a0.w += a1.w;

    float nd = g_norm_dst[node];
    float4 b = *reinterpret_cast<const float4*>(b2 + c);
    a0.x = fmaf(a0.x, nd, b.x);
    a0.y = fmaf(a0.y, nd, b.y);
    a0.z = fmaf(a0.z, nd, b.z);
    a0.w = fmaf(a0.w, nd, b.w);
    *reinterpret_cast<float4*>(out + (size_t)node * DC + c) = a0;
}

// ---------------- finalize BN stats -------------------------------------------
template<int L>
__global__ void k_finalize_stats() {
    int i = threadIdx.x;
    if (i < DIM) {
        const float* S = (L == 0) ? g_sum0 : g_sum1;
        const float* Q = (L == 0) ? g_sumsq0 : g_sumsq1;
        float inv = 1.0f / (float)NN;
        float mean = S[i] * inv;
        float var  = fmaxf(Q[i] * inv - mean * mean, 0.f);
        g_mean[i] = mean;
        g_rstd[i] = rsqrtf(var + BN_EPS);
    }
}

// ---------------- tail reset ----------------------------------------------------
__global__ void k_reset() {
    int i = blockIdx.x * blockDim.x + threadIdx.x;
    if (i < NN) {
        g_deg_out[i] = 0; g_deg_in[i] = 0; g_cursor[i] = 0;
    }
}

// ---------------- launch ---------------------------------------------------------
extern "C" void kernel_launch(void* const* d_in, const int* in_sizes, int n_in,
                              void* d_out, int out_size) {
    const float* features = (const float*)d_in[0];
    const float* W0 = (const float*)d_in[1];
    const float* b0 = (const float*)d_in[2];
    const float* W1 = (const float*)d_in[3];
    const float* b1 = (const float*)d_in[4];
    const float* W2 = (const float*)d_in[5];
    const float* b2 = (const float*)d_in[6];
    const int* src = (const int*)d_in[7];
    const int* dst = (const int*)d_in[8];
    float* out = (float*)d_out;

    const int TB = 256;
    const int gN      = (NN + TB - 1) / TB;
    const int gE      = (NE + TB - 1) / TB;
    const int gPull64 = (NN * 16 + TB - 1) / TB;
    const int gGemm   = (NN + 63) / 64;
    const int gConv   = (NN * DIM / 4 + TB - 1) / TB;

    // setup (counters arrive zeroed: zero-init first call, k_reset tail after)
    k_count<<<gE, TB>>>(src, dst);          // #1
    k_scan_norms<<<NB, SCAN_B>>>();         // #2
    k_scan_block<<<1, 128>>>();             // #3
    k_fill_csr<<<gE, TB>>>(src, dst);       // #4 (profiled slot)
    k_feat2h<<<gConv, TB>>>(features);      // #5

    // layer 1 (fused pull+GEMM): feat16 -> h1' fp16; stats->sum0
    k_fused128<0><<<gGemm, TB>>>(W0, b0);
    k_finalize_stats<0><<<1, 128>>>();

    // layer 2 (fused pull+GEMM): h1' -> h2' fp16; stats->sum1
    k_fused128<1><<<gGemm, TB>>>(W1, b1);
    k_finalize_stats<1><<<1, 128>>>();

    // layer 3: g = ((h2' - m*ns)*rs) @ W2 -> fp16 g, then pull64 + nd,b2
    k_gemm64<<<gGemm, TB>>>(W2);
    k_pull64<<<gPull64, TB>>>(out, b2);

    // leave counters zeroed for next invocation
    k_reset<<<gN, TB>>>();
}